// round 13
// baseline (speedup 1.0000x reference)
#include <cuda_runtime.h>
#include <math.h>

#define T_STEPS   32768
#define N_NEUR    1024
#define FILT_LEN  200
#define THREADS   256
#define CHUNK     1024
#define NCH       (T_STEPS / CHUNK)
#define PAD       128
#define NBUF      3
#define FTAB      1024
#define MAXSPK    4096

#define LOG_DT_F      (-6.907755278982137f)
#define NOISE_SIGMA_F (0.2f)
#define INH_INC_F     (3000.0f)

// scratch (no cudaMalloc allowed)
__device__ float          g_thr[T_STEPS];
__device__ unsigned short g_loc[T_STEPS];
__device__ int            g_cnt[NCH * 32];     // one counter per 128B line
__device__ float          g_filt[FILT_LEN];    // FIR taps
__device__ int            g_spk_t[MAXSPK];     // spike times
__device__ float          g_spk_a[MAXSPK];     // post-spike amplitudes

__global__ void init_kernel() {
    const int i = threadIdx.x;
    if (i < NCH * 32) g_cnt[i] = 0;
    if (i < FILT_LEN) g_filt[i] = expf(-((float)i) * 0.05f);
}

// ---------------------------------------------------------------------------
// Fused kernel, R9 skeleton. Block 0 = persistent scanner; blocks 1..T_STEPS
// = producers. R12 deltas vs the 186us R9 version ONLY:
//  (1) producer drops the max-pass (unshifted __expf; validated in R11),
//  (2) scanner window widened 64 -> 128 (4 thr/lane; same value-space
//      semantics and amplitude formula that passed in R9).
// ---------------------------------------------------------------------------
__global__ void __launch_bounds__(THREADS)
fused_kernel(const float* __restrict__ inputs,
             const float* __restrict__ noise_rand,
             const float* __restrict__ u_mult,
             const float* __restrict__ rand_val,
             float* __restrict__ out)
{
    const int tid  = threadIdx.x;
    const int lane = tid & 31;
    const unsigned FULL = 0xffffffffu;
    const size_t IDX_INH = (size_t)T_STEPS * N_NEUR;

    __shared__ float s_thr[NBUF][CHUNK + PAD];
    __shared__ float s_fp[FTAB + 1];
    __shared__ int   s_nspk;
    __shared__ float s_ns[8];
    __shared__ float s_wsum[8];
    __shared__ int   s_cnt[8];

    if (blockIdx.x != 0) {
        // =================== PRODUCER: row t = blockIdx.x - 1 ===============
        const int t   = blockIdx.x - 1;
        const int wid = tid >> 5;

        const float4 x4 =
            reinterpret_cast<const float4*>(inputs)[(size_t)t * (N_NEUR / 4) + tid];

        // noise tap (table'd FIR)
        float prod = 0.0f;
        if (tid < FILT_LEN) {
            int idx = t - tid;
            if (idx >= 0) prod = (noise_rand[idx] * NOISE_SIGMA_F) * g_filt[tid];
        }

        // unshifted exps (x ~ N(0,1): e^x <= ~110; ratios/sums safe) — R11-validated
        const float e0 = __expf(x4.x);
        const float e1 = __expf(x4.y);
        const float e2 = __expf(x4.z);
        const float e3 = __expf(x4.w);
        const float p0 = e0;
        const float p1 = p0 + e1;
        const float p2 = p1 + e2;
        const float p3 = p2 + e3;

        // warp: inclusive scan of p3 + butterfly reduce of noise prod
        float incl = p3;
        #pragma unroll
        for (int o = 1; o < 32; o <<= 1) {
            float n = __shfl_up_sync(FULL, incl, o);
            if (lane >= o) incl += n;
            prod += __shfl_xor_sync(FULL, prod, o);
        }
        if (lane == 31) s_wsum[wid] = incl;
        if (lane == 0)  s_ns[wid]   = prod;
        __syncthreads();

        float warp_off = 0.0f, stot = 0.0f;
        {
            float acc = 0.0f;
            #pragma unroll
            for (int i = 0; i < 8; i++) {
                if (i == wid) warp_off = acc;
                acc += s_wsum[i];
            }
            stot = acc;
        }
        float excl = __shfl_up_sync(FULL, incl, 1);
        if (lane == 0) excl = 0.0f;
        const float base = warp_off + excl;

        const float us = u_mult[t] * stot;
        int cnt = (int)((base + p0) < us) + (int)((base + p1) < us)
                + (int)((base + p2) < us) + (int)((base + p3) < us);
        #pragma unroll
        for (int o = 16; o; o >>= 1) cnt += __shfl_xor_sync(FULL, cnt, o);
        if (lane == 0) s_cnt[wid] = cnt;
        __syncthreads();

        if (tid == 0) {
            int total = 0;
            #pragma unroll
            for (int i = 0; i < 8; i++) total += s_cnt[i];
            int loc = (total >= N_NEUR) ? 0 : total;
            g_loc[t] = (unsigned short)loc;

            float c = 0.0f;
            #pragma unroll
            for (int i = 0; i < 8; i++) c += s_ns[i];

            g_thr[t] = ((logf(stot) + c) + LOG_DT_F) - logf(rand_val[t]);
            out[IDX_INH + T_STEPS + t] = c;    // noise output
        }

        // zero-fill the out_spikes row (scanner scatters the rare 1.0s)
        reinterpret_cast<float4*>(out)[(size_t)t * (N_NEUR / 4) + tid] =
            make_float4(0.0f, 0.0f, 0.0f, 0.0f);

        // release: one fence + one atomic per block
        __syncthreads();
        if (tid == 0) {
            __threadfence();
            atomicAdd(&g_cnt[(t >> 10) << 5], 1);
        }
        return;
    }

    // ======================= SCANNER (block 0) ==============================
    // F^i table, double-accurate, single fp32 rounding (0 beyond underflow)
    for (int i = tid; i <= FTAB; i += THREADS)
        s_fp[i] = (float)exp(-0.2 * (double)i);
    __syncthreads();

    // ---- prologue: stage chunk 0, then chunk 1 (+ pads of chunk 0) ----
    if (tid == 0) {
        while (*((volatile int*)&g_cnt[0]) < CHUNK) __nanosleep(256);
        __threadfence();
    }
    __syncthreads();
    for (int i = tid; i < CHUNK; i += THREADS) s_thr[0][i] = g_thr[i];
    if (tid == 0) {
        while (*((volatile int*)&g_cnt[1 << 5]) < CHUNK) __nanosleep(256);
        __threadfence();
    }
    __syncthreads();
    for (int i = tid; i < CHUNK; i += THREADS) s_thr[1][i] = g_thr[CHUNK + i];
    for (int i = tid; i < PAD;   i += THREADS) s_thr[0][CHUNK + i] = g_thr[CHUNK + i];
    __syncthreads();

    // per-lane decay constants (registers): F^(4l)..F^(4l+4), window hop F^128
    const int   l4   = lane << 2;
    const float C0   = s_fp[l4];
    const float C1   = s_fp[l4 + 1];
    const float C2   = s_fp[l4 + 2];
    const float C3   = s_fp[l4 + 3];
    const float C4   = s_fp[l4 + 4];
    const float C128 = s_fp[PAD];

    // phase-1 state (warp 0 registers; uniform across lanes)
    float Wv  = 0.0f;      // inh value entering step p
    int   p   = 0;
    int   nsp = 0;

    for (int ch = 0; ch < NCH; ++ch) {
        if (tid < 32) {
            // ---- warp 0: spike-finding scan of chunk ch (window = 128) ----
            const float* tb   = s_thr[ch % NBUF];
            const int    cb   = ch * CHUNK;
            const int    cend = cb + CHUNK;

            while (p < cend) {
                const int i0 = (p - cb) + l4;        // pads make reads safe
                const float t0 = tb[i0];
                const float t1 = tb[i0 + 1];
                const float t2 = tb[i0 + 2];
                const float t3 = tb[i0 + 3];

                const float w0 = __fmul_rn(Wv, C0);  // w_{p+l4}
                const float w1 = __fmul_rn(Wv, C1);
                const float w2 = __fmul_rn(Wv, C2);
                const float w3 = __fmul_rn(Wv, C3);
                const float w4 = __fmul_rn(Wv, C4);  // w_{p+l4+4}

                const unsigned m0 = __ballot_sync(FULL, w0 < t0);
                const unsigned m1 = __ballot_sync(FULL, w1 < t1);
                const unsigned m2 = __ballot_sync(FULL, w2 < t2);
                const unsigned m3 = __ballot_sync(FULL, w3 < t3);

                if (m0 | m1 | m2 | m3) {
                    const int j0 = m0 ? (((__ffs(m0) - 1) << 2) | 0) : 0x7fffffff;
                    const int j1 = m1 ? (((__ffs(m1) - 1) << 2) | 1) : 0x7fffffff;
                    const int j2 = m2 ? (((__ffs(m2) - 1) << 2) | 2) : 0x7fffffff;
                    const int j3 = m3 ? (((__ffs(m3) - 1) << 2) | 3) : 0x7fffffff;
                    const int j  = min(min(j0, j1), min(j2, j3));  // first spike

                    // lane (j>>2) holds w_{j+1} = its w[(j&3)+1]
                    const int b0 = (m0 >> lane) & 1;
                    const int b1 = (m1 >> lane) & 1;
                    const int b2 = (m2 >> lane) & 1;
                    const float cand = b0 ? w1 : (b1 ? w2 : (b2 ? w3 : w4));
                    const float wn   = __shfl_sync(FULL, cand, (j >> 2) & 31);
                    const float An   = __fadd_rn(wn, INH_INC_F);   // R9 formula

                    if (lane == 0 && nsp < MAXSPK) {
                        g_spk_t[nsp] = p + j;
                        g_spk_a[nsp] = An;
                    }
                    nsp++;
                    Wv = An;
                    p += j + 1;
                } else {
                    Wv = __fmul_rn(Wv, C128);
                    p += PAD;
                }
            }
        } else {
            // ---- warps 1..7: stage chunk ch+2 (+ pads of chunk ch+1) ----
            const int cn = ch + 2;
            if (cn < NCH) {
                if (lane == 0) {
                    while (*((volatile int*)&g_cnt[cn << 5]) < CHUNK)
                        __nanosleep(256);
                    __threadfence();
                }
                __syncwarp();
                float*    dm  = s_thr[cn % NBUF];
                float*    dp  = s_thr[(cn + NBUF - 1) % NBUF];
                const int off = cn * CHUNK;
                for (int i = tid - 32; i < CHUNK; i += THREADS - 32)
                    dm[i] = g_thr[off + i];
                for (int i = tid - 32; i < PAD; i += THREADS - 32)
                    dp[CHUNK + i] = g_thr[off + i];
            } else if (cn == NCH) {
                // -inf pads for the last chunk: never spikes past T
                float* dp = s_thr[(NCH - 1) % NBUF];
                for (int i = tid - 32; i < PAD; i += THREADS - 32)
                    dp[CHUNK + i] = __int_as_float(0xff800000);
            }
        }
        __syncthreads();
    }

    if (tid == 0) s_nspk = min(nsp, MAXSPK);
    __syncthreads();

    // ======================= PHASE 2: reconstruction ========================
    // inhibition[t] = A_s * F^(t - ts_s) for the last spike s with ts_s <= t
    // (0 before the first spike); one-hot scatter at spike times.
    {
        const int ns = s_nspk;
        const int t0 = tid * (T_STEPS / THREADS);
        const int t1 = t0 + (T_STEPS / THREADS);

        int lo = 0, hi = ns;
        while (lo < hi) {
            const int mid = (lo + hi) >> 1;
            if (g_spk_t[mid] < t0) lo = mid + 1; else hi = mid;
        }
        int   s    = lo - 1;
        float A2   = (s >= 0) ? g_spk_a[s] : 0.0f;
        int   bs   = (s >= 0) ? g_spk_t[s] : t0;
        int   next = (s + 1 < ns) ? g_spk_t[s + 1] : 0x7fffffff;

        for (int t = t0; t < t1; ++t) {
            float val;
            if (t == next) {
                ++s;
                A2   = g_spk_a[s];
                bs   = t;
                next = (s + 1 < ns) ? g_spk_t[s + 1] : 0x7fffffff;
                out[(size_t)t * N_NEUR + (int)g_loc[t]] = 1.0f;
                val = A2;
            } else {
                val = __fmul_rn(A2, s_fp[min(t - bs, FTAB)]);
            }
            out[IDX_INH + t] = val;
        }
    }
}

extern "C" void kernel_launch(void* const* d_in, const int* in_sizes, int n_in,
                              void* d_out, int out_size)
{
    const float* inputs     = (const float*)d_in[0];
    const float* noise_rand = (const float*)d_in[1];
    const float* u_mult     = (const float*)d_in[2];
    const float* rand_val   = (const float*)d_in[3];
    float* out = (float*)d_out;

    init_kernel<<<1, 1024>>>();
    fused_kernel<<<T_STEPS + 1, THREADS>>>(inputs, noise_rand, u_mult, rand_val, out);
}

// round 14
// speedup vs baseline: 1.5938x; 1.5938x over previous
#include <cuda_runtime.h>
#include <math.h>

#define T_STEPS   32768
#define N_NEUR    1024
#define FILT_LEN  200
#define THREADS   256
#define PAD       64
#define FTAB      1024
#define MAXSPK    4096

#define LOG_DT_F      (-6.907755278982137f)
#define NOISE_SIGMA_F (0.2f)
#define INH_INC_F     (3000.0f)

// scratch (no cudaMalloc allowed)
__device__ float          g_thr[T_STEPS];
__device__ unsigned short g_loc[T_STEPS];
__device__ float          g_filt[FILT_LEN];   // FIR taps

__global__ void init_kernel() {
    const int i = threadIdx.x;
    if (i < FILT_LEN) g_filt[i] = expf(-((float)i) * 0.05f);
}

// ---------------------------------------------------------------------------
// One block per time step t. Verbatim R9/R7 producer (validated, ~75us):
// table'd FIR, max-pass, __expf, thr = log(stot)+mp+logdt-log(r).
// ---------------------------------------------------------------------------
__global__ void __launch_bounds__(THREADS)
row_kernel(const float* __restrict__ inputs,
           const float* __restrict__ noise_rand,
           const float* __restrict__ u_mult,
           const float* __restrict__ rand_val,
           float* __restrict__ out)
{
    const int t    = blockIdx.x;
    const int tid  = threadIdx.x;
    const int lane = tid & 31;
    const int wid  = tid >> 5;
    const unsigned FULL = 0xffffffffu;
    const size_t IDX_INH = (size_t)T_STEPS * N_NEUR;

    __shared__ float s_max[8];
    __shared__ float s_ns[8];
    __shared__ float s_wsum[8];
    __shared__ int   s_cnt[8];
    __shared__ float s_b[2];

    const float4 x4 =
        reinterpret_cast<const float4*>(inputs)[(size_t)t * (N_NEUR / 4) + tid];

    // noise tap (table'd FIR)
    float prod = 0.0f;
    if (tid < FILT_LEN) {
        int idx = t - tid;
        if (idx >= 0) prod = (noise_rand[idx] * NOISE_SIGMA_F) * g_filt[tid];
    }

    // joint warp reduce: row max + noise sum
    float lm = fmaxf(fmaxf(x4.x, x4.y), fmaxf(x4.z, x4.w));
    #pragma unroll
    for (int o = 16; o; o >>= 1) {
        lm   = fmaxf(lm, __shfl_xor_sync(FULL, lm, o));
        prod += __shfl_xor_sync(FULL, prod, o);
    }
    if (lane == 0) { s_max[wid] = lm; s_ns[wid] = prod; }
    __syncthreads();
    if (tid == 0) {
        float m = s_max[0], c = s_ns[0];
        #pragma unroll
        for (int i = 1; i < 8; i++) { m = fmaxf(m, s_max[i]); c += s_ns[i]; }
        s_b[0] = c;
        s_b[1] = m + c;     // m' for inputs+noise (monotone rounding)
    }
    __syncthreads();
    const float c  = s_b[0];
    const float mp = s_b[1];

    // fast exp (args <= 0; validated in R7/R9 at rel_err 1.16e-7)
    const float e0 = __expf((x4.x + c) - mp);
    const float e1 = __expf((x4.y + c) - mp);
    const float e2 = __expf((x4.z + c) - mp);
    const float e3 = __expf((x4.w + c) - mp);
    const float p0 = e0;
    const float p1 = p0 + e1;
    const float p2 = p1 + e2;
    const float p3 = p2 + e3;

    float incl = p3;
    #pragma unroll
    for (int o = 1; o < 32; o <<= 1) {
        float n = __shfl_up_sync(FULL, incl, o);
        if (lane >= o) incl += n;
    }
    if (lane == 31) s_wsum[wid] = incl;
    __syncthreads();
    float warp_off = 0.0f, stot = 0.0f;
    {
        float acc = 0.0f;
        #pragma unroll
        for (int i = 0; i < 8; i++) {
            if (i == wid) warp_off = acc;
            acc += s_wsum[i];
        }
        stot = acc;
    }
    float excl = __shfl_up_sync(FULL, incl, 1);
    if (lane == 0) excl = 0.0f;
    const float base = warp_off + excl;

    const float us = u_mult[t] * stot;
    int cnt = (int)((base + p0) < us) + (int)((base + p1) < us)
            + (int)((base + p2) < us) + (int)((base + p3) < us);
    #pragma unroll
    for (int o = 16; o; o >>= 1) cnt += __shfl_xor_sync(FULL, cnt, o);
    if (lane == 0) s_cnt[wid] = cnt;
    __syncthreads();
    if (tid == 0) {
        int total = 0;
        #pragma unroll
        for (int i = 0; i < 8; i++) total += s_cnt[i];
        int loc = (total >= N_NEUR) ? 0 : total;
        g_loc[t] = (unsigned short)loc;
        const float logr = logf(rand_val[t]);
        g_thr[t] = ((logf(stot) + mp) + LOG_DT_F) - logr;
        out[IDX_INH + T_STEPS + t] = c;    // noise output
    }

    // zero-fill the out_spikes row (scan kernel scatters the rare 1.0s)
    reinterpret_cast<float4*>(out)[(size_t)t * (N_NEUR / 4) + tid] =
        make_float4(0.0f, 0.0f, 0.0f, 0.0f);
}

// ---------------------------------------------------------------------------
// Standalone scan + reconstruction, one block, UNCONTENDED.
//  - stage all thr into smem (float4, 8 warps)
//  - warp 0: exact R9 window-64 speculative decay scan; the spiked amplitude
//    wn = fl(Wv * s_fp[j+1]) is recomputed uniformly (bit-identical to R9's
//    shfl'd lane value: same table entry, same single rounding)
//  - spike list in smem; phase 2 (all 256 threads) reconstructs inhibition
//    and scatters one-hot spikes
// ---------------------------------------------------------------------------
__global__ void __launch_bounds__(THREADS)
scan_kernel(float* __restrict__ out)
{
    extern __shared__ char smem[];
    float* s_thr  = reinterpret_cast<float*>(smem);                     // T+PAD
    float* s_fp   = s_thr + (T_STEPS + PAD);                            // FTAB+1
    int*   s_spkt = reinterpret_cast<int*>(s_fp + (FTAB + 1));          // MAXSPK
    float* s_spka = reinterpret_cast<float*>(s_spkt + MAXSPK);          // MAXSPK
    __shared__ int s_nspk;

    const int tid  = threadIdx.x;
    const int lane = tid & 31;
    const unsigned FULL = 0xffffffffu;
    const size_t IDX_INH = (size_t)T_STEPS * N_NEUR;

    // ---- stage thr (vectorized) + F-table + pads ----
    {
        const float4* src4 = reinterpret_cast<const float4*>(g_thr);
        float4*       dst4 = reinterpret_cast<float4*>(s_thr);
        for (int i = tid; i < T_STEPS / 4; i += THREADS) dst4[i] = src4[i];
        for (int i = tid; i < PAD; i += THREADS)
            s_thr[T_STEPS + i] = __int_as_float(0xff800000);  // -inf: never spikes
        for (int i = tid; i <= FTAB; i += THREADS)
            s_fp[i] = (float)exp(-0.2 * (double)i);
    }
    __syncthreads();

    // ======================= PHASE 1: spike finding =========================
    if (tid < 32) {
        const int   l2  = lane << 1;
        const float C0  = s_fp[l2];        // F^(2l)
        const float C1  = s_fp[l2 + 1];    // F^(2l+1)
        const float C64 = s_fp[PAD];       // F^64 window hop

        float Wv  = 0.0f;                  // inh value entering step p
        int   p   = 0;
        int   nsp = 0;

        while (p < T_STEPS) {
            const float t0 = s_thr[p + l2];
            const float t1 = s_thr[p + l2 + 1];

            const float w0 = __fmul_rn(Wv, C0);
            const float w1 = __fmul_rn(Wv, C1);

            const unsigned m0 = __ballot_sync(FULL, w0 < t0);
            const unsigned m1 = __ballot_sync(FULL, w1 < t1);

            if (m0 | m1) {
                const int j0 = m0 ? ((__ffs(m0) - 1) << 1)       : 0x7fffffff;
                const int j1 = m1 ? (((__ffs(m1) - 1) << 1) | 1) : 0x7fffffff;
                const int j  = min(j0, j1);                // first spike offset

                // wn = w_{j+1}; uniform recompute == R9's shfl'd value
                const float wn = __fmul_rn(Wv, s_fp[j + 1]);
                const float An = __fadd_rn(wn, INH_INC_F);

                if (lane == 0 && nsp < MAXSPK) {
                    s_spkt[nsp] = p + j;
                    s_spka[nsp] = An;
                }
                nsp++;
                Wv = An;
                p += j + 1;
            } else {
                Wv = __fmul_rn(Wv, C64);
                p += PAD;
            }
        }
        if (tid == 0) s_nspk = min(nsp, MAXSPK);
    }
    __syncthreads();

    // ======================= PHASE 2: reconstruction ========================
    // inhibition[t] = A_s * F^(t - ts_s) for the last spike s with ts_s <= t
    // (0 before the first spike); one-hot scatter at spike times.
    {
        const int ns = s_nspk;
        const int t0 = tid * (T_STEPS / THREADS);
        const int t1 = t0 + (T_STEPS / THREADS);

        int lo = 0, hi = ns;
        while (lo < hi) {
            const int mid = (lo + hi) >> 1;
            if (s_spkt[mid] < t0) lo = mid + 1; else hi = mid;
        }
        int   s    = lo - 1;
        float A2   = (s >= 0) ? s_spka[s] : 0.0f;
        int   bs   = (s >= 0) ? s_spkt[s] : t0;
        int   next = (s + 1 < ns) ? s_spkt[s + 1] : 0x7fffffff;

        for (int t = t0; t < t1; ++t) {
            float val;
            if (t == next) {
                ++s;
                A2   = s_spka[s];
                bs   = t;
                next = (s + 1 < ns) ? s_spkt[s + 1] : 0x7fffffff;
                out[(size_t)t * N_NEUR + (int)g_loc[t]] = 1.0f;
                val = A2;
            } else {
                val = __fmul_rn(A2, s_fp[min(t - bs, FTAB)]);
            }
            out[IDX_INH + t] = val;
        }
    }
}

extern "C" void kernel_launch(void* const* d_in, const int* in_sizes, int n_in,
                              void* d_out, int out_size)
{
    const float* inputs     = (const float*)d_in[0];
    const float* noise_rand = (const float*)d_in[1];
    const float* u_mult     = (const float*)d_in[2];
    const float* rand_val   = (const float*)d_in[3];
    float* out = (float*)d_out;

    const size_t smem_bytes =
        (size_t)(T_STEPS + PAD) * sizeof(float) +     // s_thr
        (size_t)(FTAB + 1) * sizeof(float) +          // s_fp
        (size_t)MAXSPK * (sizeof(int) + sizeof(float)); // spike list

    static int configured = 0;
    if (!configured) {
        cudaFuncSetAttribute(scan_kernel,
                             cudaFuncAttributeMaxDynamicSharedMemorySize,
                             (int)smem_bytes);
        configured = 1;
    }

    init_kernel<<<1, THREADS>>>();
    row_kernel<<<T_STEPS, THREADS>>>(inputs, noise_rand, u_mult, rand_val, out);
    scan_kernel<<<1, THREADS, smem_bytes>>>(out);
}

// round 15
// speedup vs baseline: 2.1371x; 1.3409x over previous
#include <cuda_runtime.h>
#include <math.h>

#define T_STEPS   32768
#define N_NEUR    1024
#define FILT_LEN  200
#define THREADS   256
#define CHUNK     1024
#define NCH       (T_STEPS / CHUNK)
#define PAD       64
#define NBUF      3
#define FTAB      1024
#define MAXSPK    4096

#define LOG_DT_F      (-6.907755278982137f)
#define NOISE_SIGMA_F (0.2f)
#define INH_INC_F     (3000.0f)

// scratch (no cudaMalloc allowed)
__device__ float          g_thr[T_STEPS];
__device__ unsigned short g_loc[T_STEPS];
__device__ int            g_cnt[NCH * 32];     // one counter per 128B line
__device__ float          g_filt[FILT_LEN];    // FIR taps
__device__ int            g_spk_t[MAXSPK];     // spike times
__device__ float          g_spk_a[MAXSPK];     // post-spike amplitudes

__global__ void init_kernel() {
    const int i = threadIdx.x;
    if (i < NCH * 32) g_cnt[i] = 0;
    if (i < FILT_LEN) g_filt[i] = expf(-((float)i) * 0.05f);
}

// ---------------------------------------------------------------------------
// Fused kernel, R9 skeleton (186us). Block 0 = persistent scanner; blocks
// 1..T_STEPS = producers (R9 producer verbatim). R14 delta: the scanner's
// window-64 round is BRANCHLESS and uniform:
//   adv = spike ? j+1 : 64;  Wv = fl(Wv*F^adv) + (spike ? 3000 : 0)
// which is bit-identical to the validated R9/R13 semantics (fl(x)+0.0f == x
// for x >= 0), with an unconditional lane-0 spike-record store (slots beyond
// nsp are overwritten; nsp increments only on true spikes).
// ---------------------------------------------------------------------------
__global__ void __launch_bounds__(THREADS)
fused_kernel(const float* __restrict__ inputs,
             const float* __restrict__ noise_rand,
             const float* __restrict__ u_mult,
             const float* __restrict__ rand_val,
             float* __restrict__ out)
{
    const int tid  = threadIdx.x;
    const int lane = tid & 31;
    const unsigned FULL = 0xffffffffu;
    const size_t IDX_INH = (size_t)T_STEPS * N_NEUR;

    __shared__ float s_thr[NBUF][CHUNK + PAD];
    __shared__ float s_fp[FTAB + 1];
    __shared__ int   s_nspk;
    __shared__ float s_max[8];
    __shared__ float s_ns[8];
    __shared__ float s_wsum[8];
    __shared__ int   s_cnt[8];
    __shared__ float s_b[2];

    if (blockIdx.x != 0) {
        // =================== PRODUCER: row t = blockIdx.x - 1 ===============
        const int t   = blockIdx.x - 1;
        const int wid = tid >> 5;

        const float4 x4 =
            reinterpret_cast<const float4*>(inputs)[(size_t)t * (N_NEUR / 4) + tid];

        // noise tap (table'd FIR)
        float prod = 0.0f;
        if (tid < FILT_LEN) {
            int idx = t - tid;
            if (idx >= 0) prod = (noise_rand[idx] * NOISE_SIGMA_F) * g_filt[tid];
        }

        // joint warp reduce: row max + noise sum
        float lm = fmaxf(fmaxf(x4.x, x4.y), fmaxf(x4.z, x4.w));
        #pragma unroll
        for (int o = 16; o; o >>= 1) {
            lm   = fmaxf(lm, __shfl_xor_sync(FULL, lm, o));
            prod += __shfl_xor_sync(FULL, prod, o);
        }
        if (lane == 0) { s_max[wid] = lm; s_ns[wid] = prod; }
        __syncthreads();
        if (tid == 0) {
            float m = s_max[0], c = s_ns[0];
            #pragma unroll
            for (int i = 1; i < 8; i++) { m = fmaxf(m, s_max[i]); c += s_ns[i]; }
            s_b[0] = c;
            s_b[1] = m + c;     // m' for inputs+noise (monotone rounding)
        }
        __syncthreads();
        const float c  = s_b[0];
        const float mp = s_b[1];

        // fast exp (args <= 0; validated at rel_err 1.16e-7)
        const float e0 = __expf((x4.x + c) - mp);
        const float e1 = __expf((x4.y + c) - mp);
        const float e2 = __expf((x4.z + c) - mp);
        const float e3 = __expf((x4.w + c) - mp);
        const float p0 = e0;
        const float p1 = p0 + e1;
        const float p2 = p1 + e2;
        const float p3 = p2 + e3;

        float incl = p3;
        #pragma unroll
        for (int o = 1; o < 32; o <<= 1) {
            float n = __shfl_up_sync(FULL, incl, o);
            if (lane >= o) incl += n;
        }
        if (lane == 31) s_wsum[wid] = incl;
        __syncthreads();
        float warp_off = 0.0f, stot = 0.0f;
        {
            float acc = 0.0f;
            #pragma unroll
            for (int i = 0; i < 8; i++) {
                if (i == wid) warp_off = acc;
                acc += s_wsum[i];
            }
            stot = acc;
        }
        float excl = __shfl_up_sync(FULL, incl, 1);
        if (lane == 0) excl = 0.0f;
        const float base = warp_off + excl;

        const float us = u_mult[t] * stot;
        int cnt = (int)((base + p0) < us) + (int)((base + p1) < us)
                + (int)((base + p2) < us) + (int)((base + p3) < us);
        #pragma unroll
        for (int o = 16; o; o >>= 1) cnt += __shfl_xor_sync(FULL, cnt, o);
        if (lane == 0) s_cnt[wid] = cnt;
        __syncthreads();
        if (tid == 0) {
            int total = 0;
            #pragma unroll
            for (int i = 0; i < 8; i++) total += s_cnt[i];
            int loc = (total >= N_NEUR) ? 0 : total;
            g_loc[t] = (unsigned short)loc;
            const float logr = logf(rand_val[t]);
            g_thr[t] = ((logf(stot) + mp) + LOG_DT_F) - logr;
            out[IDX_INH + T_STEPS + t] = c;    // noise output
        }

        // zero-fill the out_spikes row (scanner scatters the rare 1.0s)
        reinterpret_cast<float4*>(out)[(size_t)t * (N_NEUR / 4) + tid] =
            make_float4(0.0f, 0.0f, 0.0f, 0.0f);

        // release: one fence + one atomic per block
        __syncthreads();
        if (tid == 0) {
            __threadfence();
            atomicAdd(&g_cnt[(t >> 10) << 5], 1);
        }
        return;
    }

    // ======================= SCANNER (block 0) ==============================
    // F^i table, double-accurate, single fp32 rounding (0 beyond underflow)
    for (int i = tid; i <= FTAB; i += THREADS)
        s_fp[i] = (float)exp(-0.2 * (double)i);
    __syncthreads();

    // ---- prologue: stage chunk 0, then chunk 1 (+ pads of chunk 0) ----
    if (tid == 0) {
        while (*((volatile int*)&g_cnt[0]) < CHUNK) __nanosleep(256);
        __threadfence();
    }
    __syncthreads();
    for (int i = tid; i < CHUNK; i += THREADS) s_thr[0][i] = g_thr[i];
    if (tid == 0) {
        while (*((volatile int*)&g_cnt[1 << 5]) < CHUNK) __nanosleep(256);
        __threadfence();
    }
    __syncthreads();
    for (int i = tid; i < CHUNK; i += THREADS) s_thr[1][i] = g_thr[CHUNK + i];
    for (int i = tid; i < PAD;   i += THREADS) s_thr[0][CHUNK + i] = g_thr[CHUNK + i];
    __syncthreads();

    // per-lane decay constants (registers)
    const int   l2 = lane << 1;
    const float C0 = s_fp[l2];        // F^(2l)
    const float C1 = s_fp[l2 + 1];    // F^(2l+1)

    // phase-1 state (warp 0 registers; uniform across lanes)
    float Wv  = 0.0f;      // inh value entering step p
    int   p   = 0;
    int   nsp = 0;

    for (int ch = 0; ch < NCH; ++ch) {
        if (tid < 32) {
            // ---- warp 0: BRANCHLESS spike-finding scan of chunk ch ----
            const float* tb   = s_thr[ch % NBUF];
            const int    cb   = ch * CHUNK;
            const int    cend = cb + CHUNK;

            while (p < cend) {
                const int   i0 = (p - cb) + l2;     // pads make reads safe
                const float t0 = tb[i0];
                const float t1 = tb[i0 + 1];

                const float w0 = __fmul_rn(Wv, C0);
                const float w1 = __fmul_rn(Wv, C1);

                const unsigned m0 = __ballot_sync(FULL, w0 < t0);
                const unsigned m1 = __ballot_sync(FULL, w1 < t1);
                const bool spike = (m0 | m1) != 0u;

                const int j0 = m0 ? ((__ffs(m0) - 1) << 1)       : 0x7ffffffe;
                const int j1 = m1 ? (((__ffs(m1) - 1) << 1) | 1) : 0x7ffffffe;
                const int j  = min(j0, j1);          // first spike offset if any
                const int adv = spike ? (j + 1) : PAD;   // <= PAD always

                // uniform update: Wv' = fl(Wv*F^adv) + (spike?3000:0)
                // (no-spike: +0.0f is exact identity on Wv*F^64 >= 0)
                const float wn = __fmul_rn(Wv, s_fp[adv]);
                Wv = __fadd_rn(wn, spike ? INH_INC_F : 0.0f);

                // unconditional record; only real spikes advance nsp
                if (lane == 0) {
                    g_spk_t[nsp] = p + j;
                    g_spk_a[nsp] = Wv;
                }
                nsp += (int)spike;
                p   += adv;
            }
        } else {
            // ---- warps 1..7: stage chunk ch+2 (+ pads of chunk ch+1) ----
            const int cn = ch + 2;
            if (cn < NCH) {
                if (lane == 0) {
                    while (*((volatile int*)&g_cnt[cn << 5]) < CHUNK)
                        __nanosleep(256);
                    __threadfence();
                }
                __syncwarp();
                float*    dm  = s_thr[cn % NBUF];
                float*    dp  = s_thr[(cn + NBUF - 1) % NBUF];
                const int off = cn * CHUNK;
                for (int i = tid - 32; i < CHUNK; i += THREADS - 32)
                    dm[i] = g_thr[off + i];
                for (int i = tid - 32; i < PAD; i += THREADS - 32)
                    dp[CHUNK + i] = g_thr[off + i];
            } else if (cn == NCH) {
                // -inf pads for the last chunk: never spikes past T
                float* dp = s_thr[(NCH - 1) % NBUF];
                for (int i = tid - 32; i < PAD; i += THREADS - 32)
                    dp[CHUNK + i] = __int_as_float(0xff800000);
            }
        }
        __syncthreads();
    }

    if (tid == 0) s_nspk = min(nsp, MAXSPK);
    __syncthreads();

    // ======================= PHASE 2: reconstruction ========================
    // inhibition[t] = A_s * F^(t - ts_s) for the last spike s with ts_s <= t
    // (0 before the first spike); one-hot scatter at spike times.
    {
        const int ns = s_nspk;
        const int t0 = tid * (T_STEPS / THREADS);
        const int t1 = t0 + (T_STEPS / THREADS);

        int lo = 0, hi = ns;
        while (lo < hi) {
            const int mid = (lo + hi) >> 1;
            if (g_spk_t[mid] < t0) lo = mid + 1; else hi = mid;
        }
        int   s    = lo - 1;
        float A2   = (s >= 0) ? g_spk_a[s] : 0.0f;
        int   bs   = (s >= 0) ? g_spk_t[s] : t0;
        int   next = (s + 1 < ns) ? g_spk_t[s + 1] : 0x7fffffff;

        for (int t = t0; t < t1; ++t) {
            float val;
            if (t == next) {
                ++s;
                A2   = g_spk_a[s];
                bs   = t;
                next = (s + 1 < ns) ? g_spk_t[s + 1] : 0x7fffffff;
                out[(size_t)t * N_NEUR + (int)g_loc[t]] = 1.0f;
                val = A2;
            } else {
                val = __fmul_rn(A2, s_fp[min(t - bs, FTAB)]);
            }
            out[IDX_INH + t] = val;
        }
    }
}

extern "C" void kernel_launch(void* const* d_in, const int* in_sizes, int n_in,
                              void* d_out, int out_size)
{
    const float* inputs     = (const float*)d_in[0];
    const float* noise_rand = (const float*)d_in[1];
    const float* u_mult     = (const float*)d_in[2];
    const float* rand_val   = (const float*)d_in[3];
    float* out = (float*)d_out;

    init_kernel<<<1, 1024>>>();
    fused_kernel<<<T_STEPS + 1, THREADS>>>(inputs, noise_rand, u_mult, rand_val, out);
}